// round 5
// baseline (speedup 1.0000x reference)
#include <cuda_runtime.h>
#include <cuda_bf16.h>
#include <cstdint>

// Gather: out[i, y, x, c] = logits[i * N_SP + segments[i, y, x], c]
//   logits:   [16*512, 5] fp32 (10 KB per image, staged in smem)
//   segments: [16, 512, 512] int32 (8 KB tile per block, staged in smem)
//   out:      [16, 512, 512, 5] fp32
//
// R5: hot loop = smem gather (LDS) + conflict-free STS into a double-buffered
// 8 KB staging tile; the 84 MB output stream is drained by 1D TMA bulk stores
// (cp.async.bulk.global.shared::cta), taking the store wavefronts off the
// SM-side L1tex path that R2-R4 showed pinned at 53-65%.

#define N_IMG 16
#define SIZE  512
#define N_SP  512
#define WAY   5
#define PIX_PER_IMG    (SIZE * SIZE)            // 262144
#define VEC_PER_IMG    (PIX_PER_IMG * WAY / 4)  // 327680 float4
#define LOGITS_PER_IMG (N_SP * WAY)             // 2560 floats = 10 KB

#define THREADS 512
#define ITERS 5
#define VEC_PER_BLOCK (THREADS * ITERS)         // 2560 float4
#define PIX_PER_BLOCK (VEC_PER_BLOCK * 4 / WAY) // 2048 pixels
#define BLOCKS_PER_IMG (VEC_PER_IMG / VEC_PER_BLOCK) // 128
#define CHUNK_BYTES (THREADS * 16)              // 8192 per iter

// per-iteration float step = 4*THREADS = 2048 = 5*409 + 3
#define P_STEP 409
#define R_STEP 3

__device__ __forceinline__ uint32_t smem_addr_u32(const void* p) {
    uint32_t a;
    asm("{ .reg .u64 t; cvta.to.shared.u64 t, %1; cvt.u32.u64 %0, t; }"
        : "=r"(a) : "l"(p));
    return a;
}

__global__ void __launch_bounds__(THREADS)
sp_gather_kernel5(const float* __restrict__ logits,
                  const int* __restrict__ seg,
                  float4* __restrict__ out)
{
    __shared__ __align__(16)  float  s_logits[LOGITS_PER_IMG];
    __shared__ __align__(16)  int    s_seg[PIX_PER_BLOCK + 4];
    __shared__ __align__(128) float4 s_out[2][THREADS];   // 2 x 8 KB staging

    const int img = blockIdx.y;
    const int blk = blockIdx.x;
    const int tid = threadIdx.x;

    // ---- Staging: all global reads, fully coalesced ----
    {
        const float4* lt = (const float4*)(logits + img * LOGITS_PER_IMG);
        float4* st = (float4*)s_logits;
        st[tid] = lt[tid];                          // 512 of 640
        if (tid < LOGITS_PER_IMG / 4 - THREADS)     // remaining 128
            st[THREADS + tid] = lt[THREADS + tid];

        const int4* sg = (const int4*)(seg + img * PIX_PER_IMG
                                           + blk * PIX_PER_BLOCK);
        ((int4*)s_seg)[tid] = sg[tid];              // 2048 ints
        if (tid == 0) s_seg[PIX_PER_BLOCK] = 0;     // pad (value unused)
    }
    __syncthreads();

    // ---- Hot loop: gather -> STS staging -> TMA bulk store (double-buffered) ----
    float4* out_blk = out + (size_t)img * VEC_PER_IMG + (size_t)blk * VEC_PER_BLOCK;

    int floc = tid << 2;           // local float index
    int p = floc / 5;              // local pixel
    int r = floc - 5 * p;          // channel remainder 0..4

#pragma unroll
    for (int it = 0; it < ITERS; ++it) {
        // Ensure the staging buffer we're about to overwrite has been drained.
        if (it >= 2) {
            if (tid == 0)
                asm volatile("cp.async.bulk.wait_group 1;" ::: "memory");
            __syncthreads();
        }

        int s0 = s_seg[p];
        int s1 = s_seg[p + 1];
        int m  = 5 - r;
        int b0 = s0 * WAY + r;
        int b1 = s1 * WAY + r - 5;

        float v0 = s_logits[((0 < m) ? b0 : b1) + 0];
        float v1 = s_logits[((1 < m) ? b0 : b1) + 1];
        float v2 = s_logits[((2 < m) ? b0 : b1) + 2];
        float v3 = s_logits[((3 < m) ? b0 : b1) + 3];

        s_out[it & 1][tid] = make_float4(v0, v1, v2, v3);
        __syncthreads();

        if (tid == 0) {
            asm volatile("fence.proxy.async.shared::cta;" ::: "memory");
            uint32_t src = smem_addr_u32(&s_out[it & 1][0]);
            const float4* dst = out_blk + it * THREADS;
            asm volatile(
                "cp.async.bulk.global.shared::cta.bulk_group [%0], [%1], %2;"
                :: "l"(dst), "r"(src), "n"(CHUNK_BYTES) : "memory");
            asm volatile("cp.async.bulk.commit_group;" ::: "memory");
        }

        r += R_STEP;
        p += P_STEP;
        if (r >= 5) { r -= 5; p += 1; }
    }

    // Drain remaining bulk stores before block exit.
    if (tid == 0)
        asm volatile("cp.async.bulk.wait_group 0;" ::: "memory");
}

extern "C" void kernel_launch(void* const* d_in, const int* in_sizes, int n_in,
                              void* d_out, int out_size)
{
    const float* logits = (const float*)d_in[0];
    const int*   seg    = (const int*)d_in[1];
    float4*      out    = (float4*)d_out;

    dim3 grid(BLOCKS_PER_IMG, N_IMG);
    sp_gather_kernel5<<<grid, THREADS>>>(logits, seg, out);
}

// round 6
// speedup vs baseline: 1.0726x; 1.0726x over previous
#include <cuda_runtime.h>
#include <cuda_bf16.h>

// Gather: out[i, y, x, c] = logits[i * N_SP + segments[i, y, x], c]
//   logits:   [16*512, 5] fp32 (10 KB per image, staged in smem, pre-scaled x5)
//   segments: [16, 512, 512] int32 (2048-pixel tile staged per block, values x5)
//   out:      [16, 512, 512, 5] fp32
//
// R6: R4 structure (direct coalesced STG; TMA store regressed in R5), with
// THREADS=320 so the per-iter float stride (1280) is divisible by 5:
//  - channel remainder r is a per-thread CONSTANT (no carry logic in loop)
//  - all iterations' seg addresses are base + compile-time offsets -> the
//    scheduler can pipeline every seg LDS and gather LDS across iters
//  - seg staged pre-multiplied by WAY (saves IMADs in the hot loop)
//  - s1 seg load predicated off for lanes with r<=1 (value provably unused)

#define N_IMG 16
#define SIZE  512
#define N_SP  512
#define WAY   5
#define PIX_PER_IMG    (SIZE * SIZE)            // 262144
#define VEC_PER_IMG    (PIX_PER_IMG * WAY / 4)  // 327680 float4
#define LOGITS_PER_IMG (N_SP * WAY)             // 2560 floats = 10 KB

#define THREADS 320
#define ITERS 8
#define VEC_PER_BLOCK  (THREADS * ITERS)        // 2560 float4 = 10240 floats
#define PIX_PER_BLOCK  (VEC_PER_BLOCK * 4 / WAY)// 2048 pixels exactly
#define PIX_PER_ITER   (THREADS * 4 / WAY)      // 256 pixels (exact: 1280/5)
#define BLOCKS_PER_IMG (VEC_PER_IMG / VEC_PER_BLOCK) // 128

__global__ void __launch_bounds__(THREADS)
sp_gather_kernel6(const float* __restrict__ logits,
                  const int* __restrict__ seg,
                  float4* __restrict__ out)
{
    __shared__ __align__(16) float s_logits[LOGITS_PER_IMG];
    __shared__ __align__(16) int   s_seg5[PIX_PER_BLOCK + 4]; // pre-scaled x5, +pad

    const int img = blockIdx.y;
    const int blk = blockIdx.x;
    const int tid = threadIdx.x;

    // ---- Staging (coalesced; the only global reads) ----
    {
        const float4* lt = (const float4*)(logits + img * LOGITS_PER_IMG);
        float4* st = (float4*)s_logits;
        // 640 float4s over 320 threads: 2 rounds
        st[tid]           = lt[tid];
        st[tid + THREADS] = lt[tid + THREADS];

        const int4* sg = (const int4*)(seg + img * PIX_PER_IMG
                                           + blk * PIX_PER_BLOCK);
        int4* ss = (int4*)s_seg5;
        // 512 int4s over 320 threads: 2 rounds (second partial), scale by 5
        {
            int4 a = sg[tid];
            a.x *= WAY; a.y *= WAY; a.z *= WAY; a.w *= WAY;
            ss[tid] = a;
            if (tid < PIX_PER_BLOCK / 4 - THREADS) {   // 512-320 = 192
                int4 b = sg[tid + THREADS];
                b.x *= WAY; b.y *= WAY; b.z *= WAY; b.w *= WAY;
                ss[tid + THREADS] = b;
            }
        }
        if (tid == 0) s_seg5[PIX_PER_BLOCK] = 0;       // pad (never selected)
    }
    __syncthreads();

    // ---- Hot loop: smem gather + coalesced STG.128 ----
    float4* out_img = out + (size_t)img * VEC_PER_IMG;
    const int jbase = blk * VEC_PER_BLOCK + tid;

    const int floc = tid << 2;            // 0..1276
    const int p0   = floc / 5;            // 0..255 (one small div per thread)
    const int r    = floc - 5 * p0;       // constant channel remainder, 0..4
    const int m    = 5 - r;               // floats taken from pixel p (1..5)
    const bool need_s1 = (r >= 2);        // s1 used only when m < 4

#pragma unroll
    for (int it = 0; it < ITERS; ++it) {
        const int p = p0 + it * PIX_PER_ITER;     // compile-time offsets
        int b0 = s_seg5[p] + r;                   // base for pixel p
        int b1 = need_s1 ? (s_seg5[p + 1] + r - 5) : 0;

        float v0 = s_logits[((0 < m) ? b0 : b1) + 0];
        float v1 = s_logits[((1 < m) ? b0 : b1) + 1];
        float v2 = s_logits[((2 < m) ? b0 : b1) + 2];
        float v3 = s_logits[((3 < m) ? b0 : b1) + 3];

        out_img[jbase + it * THREADS] = make_float4(v0, v1, v2, v3);
    }
}

extern "C" void kernel_launch(void* const* d_in, const int* in_sizes, int n_in,
                              void* d_out, int out_size)
{
    const float* logits = (const float*)d_in[0];
    const int*   seg    = (const int*)d_in[1];
    float4*      out    = (float4*)d_out;

    dim3 grid(BLOCKS_PER_IMG, N_IMG);
    sp_gather_kernel6<<<grid, THREADS>>>(logits, seg, out);
}